// round 1
// baseline (speedup 1.0000x reference)
#include <cuda_runtime.h>

static constexpr int NB  = 64;     // batch
static constexpr int PP  = 196;    // spatial positions
static constexpr int EE  = 2048;   // feature dim
static constexpr int DD  = 256;    // hidden
static constexpr int HH  = 256;    // attention hidden
static constexpr int EMB = 256;    // embedding
static constexpr int VV  = 10000;  // vocab
static constexpr int LL  = 32;     // caption length
static constexpr int TT  = 31;     // timesteps
static constexpr int XK  = EMB + EE + DD;  // 2560
static constexpr int G4  = 4 * DD;         // 1024
static constexpr int KC  = 10;             // split-K chunks for gates gemm

__device__ int   g_order[NB];
__device__ int   g_target[NB];
__device__ float g_fe[NB * PP * HH];       // 12.8 MB
__device__ float g_mean[NB * EE];
__device__ float g_h[NB * DD];
__device__ float g_c[NB * DD];
__device__ float g_w[NB * PP];
__device__ float g_x[NB * XK];
__device__ float g_gp[KC * NB * G4];       // split-K partials for gates
__device__ float g_gatep[2 * NB * EE];     // split-K partials for gate pre-activation

__device__ __forceinline__ float sigf(float x) { return 1.0f / (1.0f + expf(-x)); }

// ---------------------------------------------------------------------------
// K0: stable descending counting sort of lengths (matches jnp.argsort(-len))
// ---------------------------------------------------------------------------
__global__ void k_order(const int* __restrict__ caplen) {
    if (threadIdx.x == 0) {
        int idx = 0;
        for (int v = LL; v >= 1; --v) {
            for (int i = 0; i < NB; ++i) {
                if (caplen[i] == v) {
                    g_order[idx]  = i;
                    g_target[idx] = v - 1;
                    ++idx;
                }
            }
        }
    }
}

// ---------------------------------------------------------------------------
// K1: mean over positions (reads all of feat once)
// ---------------------------------------------------------------------------
__global__ void k_mean(const float* __restrict__ feat) {
    int b = blockIdx.x;
    int e = blockIdx.y * 256 + threadIdx.x;
    const float* base = feat + (size_t)g_order[b] * PP * EE + e;
    float s = 0.f;
    #pragma unroll 4
    for (int p = 0; p < PP; ++p) s += base[(size_t)p * EE];
    g_mean[b * EE + e] = s * (1.0f / PP);
}

// ---------------------------------------------------------------------------
// K2: h0 = mean @ W_hid + b_hid ; c0 = mean @ W_cell + b_cell
// ---------------------------------------------------------------------------
__global__ void k_init(const float* __restrict__ W_hid, const float* __restrict__ b_hid,
                       const float* __restrict__ W_cell, const float* __restrict__ b_cell) {
    int b = blockIdx.x, j = threadIdx.x;
    __shared__ float sm[EE];
    for (int e = j; e < EE; e += 256) sm[e] = g_mean[b * EE + e];
    __syncthreads();
    float h = b_hid[j], c = b_cell[j];
    #pragma unroll 4
    for (int e = 0; e < EE; ++e) {
        float m = sm[e];
        h += m * W_hid[e * DD + j];
        c += m * W_cell[e * DD + j];
    }
    g_h[b * DD + j] = h;
    g_c[b * DD + j] = c;
}

// ---------------------------------------------------------------------------
// K3: fe = feat[order] @ Wf + bf.  SGEMM M=12544 K=2048 N=256.
// 128x128 block tile, BK=8, 8x8 microtile, 256 threads.
// ---------------------------------------------------------------------------
__global__ void k_fe(const float* __restrict__ feat, const float* __restrict__ Wf,
                     const float* __restrict__ bf) {
    __shared__ float As[8][136];
    __shared__ float Bs[8][128];
    __shared__ size_t rowoff[128];
    int tid = threadIdx.x;
    int mb = blockIdx.x, nb = blockIdx.y;

    if (tid < 128) {
        int gm = mb * 128 + tid;
        int b = gm / PP, p = gm % PP;
        rowoff[tid] = ((size_t)g_order[b] * PP + p) * EE;
    }
    float acc[8][8];
    #pragma unroll
    for (int i = 0; i < 8; ++i)
        #pragma unroll
        for (int j = 0; j < 8; ++j) acc[i][j] = 0.f;

    int rbase = (tid >> 4) * 8, cbase = (tid & 15) * 8;
    __syncthreads();

    for (int k0 = 0; k0 < EE; k0 += 8) {
        {
            int r = tid >> 1, kq = (tid & 1) * 4;
            float4 av = *(const float4*)(feat + rowoff[r] + k0 + kq);
            As[kq + 0][r] = av.x; As[kq + 1][r] = av.y;
            As[kq + 2][r] = av.z; As[kq + 3][r] = av.w;
        }
        {
            int kk = tid >> 5, n = (tid & 31) * 4;
            *(float4*)&Bs[kk][n] = *(const float4*)(Wf + (size_t)(k0 + kk) * HH + nb * 128 + n);
        }
        __syncthreads();
        #pragma unroll
        for (int kk = 0; kk < 8; ++kk) {
            float a[8], bv[8];
            *(float4*)(a)     = *(float4*)&As[kk][rbase];
            *(float4*)(a + 4) = *(float4*)&As[kk][rbase + 4];
            *(float4*)(bv)     = *(float4*)&Bs[kk][cbase];
            *(float4*)(bv + 4) = *(float4*)&Bs[kk][cbase + 4];
            #pragma unroll
            for (int i = 0; i < 8; ++i)
                #pragma unroll
                for (int j = 0; j < 8; ++j) acc[i][j] += a[i] * bv[j];
        }
        __syncthreads();
    }
    #pragma unroll
    for (int i = 0; i < 8; ++i) {
        int gm = mb * 128 + rbase + i;
        #pragma unroll
        for (int j = 0; j < 8; ++j) {
            int gn = nb * 128 + cbase + j;
            g_fe[(size_t)gm * HH + gn] = acc[i][j] + bf[gn];
        }
    }
}

// ---------------------------------------------------------------------------
// K4 (per step): attention scores + softmax. One block per batch row.
// ---------------------------------------------------------------------------
__global__ void k_att(const float* __restrict__ Wh, const float* __restrict__ bh,
                      const float* __restrict__ We, const float* __restrict__ be,
                      int t, float* __restrict__ out_att) {
    int b = blockIdx.x, tid = threadIdx.x;
    int lane = tid & 31, wid = tid >> 5;
    __shared__ float sh[DD], she[HH], se[256], red[8];

    sh[tid] = g_h[b * DD + tid];
    __syncthreads();

    float acc = bh[tid];
    #pragma unroll 8
    for (int k = 0; k < DD; ++k) acc += sh[k] * Wh[k * HH + tid];
    she[tid] = acc;
    __syncthreads();

    const float* febase = g_fe + (size_t)b * PP * HH;
    for (int p = wid; p < PP; p += 8) {
        const float* fr = febase + p * HH;
        float s = 0.f;
        #pragma unroll
        for (int j = lane; j < HH; j += 32) {
            float v = fr[j] + she[j];
            s += fmaxf(v, 0.f) * We[j];
        }
        #pragma unroll
        for (int o = 16; o; o >>= 1) s += __shfl_xor_sync(0xffffffffu, s, o);
        if (lane == 0) se[p] = s + be[0];
    }
    __syncthreads();

    // softmax over 196
    float v = (tid < PP) ? se[tid] : -3.4e38f;
    float m = v;
    #pragma unroll
    for (int o = 16; o; o >>= 1) m = fmaxf(m, __shfl_xor_sync(0xffffffffu, m, o));
    if (lane == 0) red[wid] = m;
    __syncthreads();
    if (tid == 0) {
        float mm = red[0];
        for (int i = 1; i < 8; ++i) mm = fmaxf(mm, red[i]);
        red[0] = mm;
    }
    __syncthreads();
    float mx = red[0];
    __syncthreads();

    float ex = (tid < PP) ? expf(v - mx) : 0.f;
    float s2 = ex;
    #pragma unroll
    for (int o = 16; o; o >>= 1) s2 += __shfl_xor_sync(0xffffffffu, s2, o);
    if (lane == 0) red[wid] = s2;
    __syncthreads();
    if (tid == 0) {
        float ss = 0.f;
        for (int i = 0; i < 8; ++i) ss += red[i];
        red[0] = ss;
    }
    __syncthreads();
    float inv = 1.0f / red[0];
    if (tid < PP) {
        float w = ex * inv;
        g_w[b * PP + tid] = w;
        out_att[((size_t)b * TT + t) * PP + tid] = (g_target[b] > t) ? w : 0.f;
    }
}

// ---------------------------------------------------------------------------
// K5 (per step): gate pre-activation h @ W_gate  (64 x 256 x 2048), split-K=2.
// BM=64 BN=64 BK=16, 4x4 microtile, 256 threads. Grid (32, 2).
// ---------------------------------------------------------------------------
__global__ void k_gpre(const float* __restrict__ W_gate) {
    __shared__ float As[16][68];
    __shared__ float Bs[16][64];
    int tid = threadIdx.x;
    int nb = blockIdx.x, kc = blockIdx.y;
    int kbase = kc * 128;
    float acc[4][4] = {};
    int rb = (tid >> 4) * 4, cb = (tid & 15) * 4;

    for (int kt = 0; kt < 128; kt += 16) {
        {
            int r = tid >> 2, kk = (tid & 3) * 4;
            float4 av = *(const float4*)(g_h + r * DD + kbase + kt + kk);
            As[kk + 0][r] = av.x; As[kk + 1][r] = av.y;
            As[kk + 2][r] = av.z; As[kk + 3][r] = av.w;
        }
        {
            int kk = tid >> 4, n = (tid & 15) * 4;
            *(float4*)&Bs[kk][n] =
                *(const float4*)(W_gate + (size_t)(kbase + kt + kk) * EE + nb * 64 + n);
        }
        __syncthreads();
        #pragma unroll
        for (int kk = 0; kk < 16; ++kk) {
            float a[4], bv[4];
            *(float4*)a  = *(float4*)&As[kk][rb];
            *(float4*)bv = *(float4*)&Bs[kk][cb];
            #pragma unroll
            for (int i = 0; i < 4; ++i)
                #pragma unroll
                for (int j = 0; j < 4; ++j) acc[i][j] += a[i] * bv[j];
        }
        __syncthreads();
    }
    #pragma unroll
    for (int i = 0; i < 4; ++i)
        #pragma unroll
        for (int j = 0; j < 4; ++j)
            g_gatep[((size_t)kc * NB + rb + i) * EE + nb * 64 + cb + j] = acc[i][j];
}

// ---------------------------------------------------------------------------
// K6 (per step): ctx = sigmoid(gate) * sum_p w_p feat_p ; assemble x vector.
// Grid (64 batch, 8 e-chunks), 256 threads.
// ---------------------------------------------------------------------------
__global__ void k_ctx(const float* __restrict__ feat, const float* __restrict__ b_gate,
                      const float* __restrict__ emb, const int* __restrict__ tok, int t) {
    int b = blockIdx.x, tid = threadIdx.x;
    __shared__ float sh[DD];
    __shared__ float sw[PP];
    sh[tid] = g_h[b * DD + tid];
    if (tid < PP) sw[tid] = g_w[b * PP + tid];
    __syncthreads();

    int e = blockIdx.y * 256 + tid;
    float gpre = b_gate[e] + g_gatep[(size_t)b * EE + e] + g_gatep[((size_t)NB + b) * EE + e];

    const float* fb = feat + (size_t)g_order[b] * PP * EE + e;
    float s0 = 0.f, s1 = 0.f, s2 = 0.f, s3 = 0.f;
    #pragma unroll 4
    for (int p = 0; p < PP; p += 4) {
        s0 += sw[p + 0] * fb[(size_t)(p + 0) * EE];
        s1 += sw[p + 1] * fb[(size_t)(p + 1) * EE];
        s2 += sw[p + 2] * fb[(size_t)(p + 2) * EE];
        s3 += sw[p + 3] * fb[(size_t)(p + 3) * EE];
    }
    float ctx = ((s0 + s1) + (s2 + s3)) * sigf(gpre);
    g_x[b * XK + EMB + e] = ctx;

    if (blockIdx.y == 0) {
        int token = tok[g_order[b] * LL + t];
        g_x[b * XK + tid] = emb[(size_t)token * EMB + tid];
        g_x[b * XK + EMB + EE + tid] = sh[tid];
    }
}

// ---------------------------------------------------------------------------
// K7 (per step): gates GEMM  [emb,ctx,h](64x2560) @ [W_ih;W_hh](2560x1024),
// split-K into 10 chunks of 256 (deterministic partials). Grid (16, 10).
// ---------------------------------------------------------------------------
__global__ void k_gates(const float* __restrict__ W_ih, const float* __restrict__ W_hh) {
    __shared__ float As[16][68];
    __shared__ float Bs[16][64];
    int tid = threadIdx.x;
    int nb = blockIdx.x, kc = blockIdx.y;
    int k0g = kc * 256;
    const float* wbase = (kc < 9) ? (W_ih + (size_t)k0g * G4) : W_hh;
    float acc[4][4] = {};
    int rb = (tid >> 4) * 4, cb = (tid & 15) * 4;

    for (int kt = 0; kt < 256; kt += 16) {
        {
            int r = tid >> 2, kk = (tid & 3) * 4;
            float4 av = *(const float4*)(g_x + r * XK + k0g + kt + kk);
            As[kk + 0][r] = av.x; As[kk + 1][r] = av.y;
            As[kk + 2][r] = av.z; As[kk + 3][r] = av.w;
        }
        {
            int kk = tid >> 4, n = (tid & 15) * 4;
            *(float4*)&Bs[kk][n] = *(const float4*)(wbase + (size_t)(kt + kk) * G4 + nb * 64 + n);
        }
        __syncthreads();
        #pragma unroll
        for (int kk = 0; kk < 16; ++kk) {
            float a[4], bv[4];
            *(float4*)a  = *(float4*)&As[kk][rb];
            *(float4*)bv = *(float4*)&Bs[kk][cb];
            #pragma unroll
            for (int i = 0; i < 4; ++i)
                #pragma unroll
                for (int j = 0; j < 4; ++j) acc[i][j] += a[i] * bv[j];
        }
        __syncthreads();
    }
    #pragma unroll
    for (int i = 0; i < 4; ++i)
        #pragma unroll
        for (int j = 0; j < 4; ++j)
            g_gp[((size_t)kc * NB + rb + i) * G4 + nb * 64 + cb + j] = acc[i][j];
}

// ---------------------------------------------------------------------------
// K8 (per step): LSTM pointwise (sums split-K partials + biases; masked update)
// ---------------------------------------------------------------------------
__global__ void k_lstm(const float* __restrict__ b_ih, const float* __restrict__ b_hh, int t) {
    int b = blockIdx.x, j = threadIdx.x;
    float gi = b_ih[j] + b_hh[j];
    float gf = b_ih[DD + j] + b_hh[DD + j];
    float gg = b_ih[2 * DD + j] + b_hh[2 * DD + j];
    float go = b_ih[3 * DD + j] + b_hh[3 * DD + j];
    #pragma unroll
    for (int kc = 0; kc < KC; ++kc) {
        const float* p = g_gp + ((size_t)kc * NB + b) * G4;
        gi += p[j];
        gf += p[DD + j];
        gg += p[2 * DD + j];
        go += p[3 * DD + j];
    }
    float c = g_c[b * DD + j];
    float cn = sigf(gf) * c + sigf(gi) * tanhf(gg);
    float hn = sigf(go) * tanhf(cn);
    if (g_target[b] > t) {
        g_h[b * DD + j] = hn;
        g_c[b * DD + j] = cn;
    }
}

// ---------------------------------------------------------------------------
// K9 (per step): head GEMM  h(64x256) @ W_head(256x10000), masked+bias write.
// BM=64 BN=64 BK=16, grid 157 blocks.
// ---------------------------------------------------------------------------
__global__ void k_head(const float* __restrict__ W_head, const float* __restrict__ b_head,
                       int t, float* __restrict__ out) {
    __shared__ float As[16][68];
    __shared__ float Bs[16][64];
    int tid = threadIdx.x, nb = blockIdx.x;
    int n0 = nb * 64;
    float acc[4][4] = {};
    int rb = (tid >> 4) * 4, cb = (tid & 15) * 4;

    for (int k0 = 0; k0 < DD; k0 += 16) {
        {
            int r = tid >> 2, kk = (tid & 3) * 4;
            float4 av = *(const float4*)(g_h + r * DD + k0 + kk);
            As[kk + 0][r] = av.x; As[kk + 1][r] = av.y;
            As[kk + 2][r] = av.z; As[kk + 3][r] = av.w;
        }
        {
            int kk = tid >> 4, n = (tid & 15) * 4;
            int gn = n0 + n;
            float4 bv;
            if (gn + 3 < VV) {
                bv = *(const float4*)(W_head + (size_t)(k0 + kk) * VV + gn);
            } else {
                bv.x = (gn + 0 < VV) ? W_head[(size_t)(k0 + kk) * VV + gn + 0] : 0.f;
                bv.y = (gn + 1 < VV) ? W_head[(size_t)(k0 + kk) * VV + gn + 1] : 0.f;
                bv.z = (gn + 2 < VV) ? W_head[(size_t)(k0 + kk) * VV + gn + 2] : 0.f;
                bv.w = (gn + 3 < VV) ? W_head[(size_t)(k0 + kk) * VV + gn + 3] : 0.f;
            }
            *(float4*)&Bs[kk][n] = bv;
        }
        __syncthreads();
        #pragma unroll
        for (int kk = 0; kk < 16; ++kk) {
            float a[4], bv[4];
            *(float4*)a  = *(float4*)&As[kk][rb];
            *(float4*)bv = *(float4*)&Bs[kk][cb];
            #pragma unroll
            for (int i = 0; i < 4; ++i)
                #pragma unroll
                for (int j = 0; j < 4; ++j) acc[i][j] += a[i] * bv[j];
        }
        __syncthreads();
    }
    #pragma unroll
    for (int i = 0; i < 4; ++i) {
        int b = rb + i;
        bool msk = (g_target[b] > t);
        size_t rowbase = ((size_t)b * TT + t) * VV;
        #pragma unroll
        for (int j = 0; j < 4; ++j) {
            int gn = n0 + cb + j;
            if (gn < VV) out[rowbase + gn] = msk ? (acc[i][j] + b_head[gn]) : 0.f;
        }
    }
}

// ---------------------------------------------------------------------------
extern "C" void kernel_launch(void* const* d_in, const int* in_sizes, int n_in,
                              void* d_out, int out_size) {
    const float* feat   = (const float*)d_in[0];
    const int*   tok    = (const int*)d_in[1];
    const int*   caplen = (const int*)d_in[2];
    const float* Wf     = (const float*)d_in[3];
    const float* bf     = (const float*)d_in[4];
    const float* Wh     = (const float*)d_in[5];
    const float* bh     = (const float*)d_in[6];
    const float* We     = (const float*)d_in[7];
    const float* be     = (const float*)d_in[8];
    const float* emb    = (const float*)d_in[9];
    const float* W_ih   = (const float*)d_in[10];
    const float* b_ih   = (const float*)d_in[11];
    const float* W_hh   = (const float*)d_in[12];
    const float* b_hh   = (const float*)d_in[13];
    const float* W_hid  = (const float*)d_in[14];
    const float* b_hid  = (const float*)d_in[15];
    const float* W_cell = (const float*)d_in[16];
    const float* b_cell = (const float*)d_in[17];
    const float* W_gate = (const float*)d_in[18];
    const float* b_gate = (const float*)d_in[19];
    const float* W_head = (const float*)d_in[20];
    const float* b_head = (const float*)d_in[21];

    float* out = (float*)d_out;
    float* out_att = out + (size_t)NB * TT * VV;

    k_order<<<1, 32>>>(caplen);
    k_mean<<<dim3(NB, 8), 256>>>(feat);
    k_init<<<NB, 256>>>(W_hid, b_hid, W_cell, b_cell);
    k_fe<<<dim3(98, 2), 256>>>(feat, Wf, bf);

    for (int t = 0; t < TT; ++t) {
        k_att<<<NB, 256>>>(Wh, bh, We, be, t, out_att);
        k_gpre<<<dim3(32, 2), 256>>>(W_gate);
        k_ctx<<<dim3(NB, 8), 256>>>(feat, b_gate, emb, tok, t);
        k_gates<<<dim3(16, 10), 256>>>(W_ih, W_hh);
        k_lstm<<<NB, 256>>>(b_ih, b_hh, t);
        k_head<<<157, 256>>>(W_head, b_head, t, out);
    }
}

// round 3
// speedup vs baseline: 1.2585x; 1.2585x over previous
#include <cuda_runtime.h>

static constexpr int NB  = 64;     // batch
static constexpr int PP  = 196;    // spatial positions
static constexpr int EE  = 2048;   // feature dim
static constexpr int DD  = 256;    // hidden
static constexpr int HH  = 256;    // attention hidden
static constexpr int EMB = 256;    // embedding
static constexpr int VV  = 10000;  // vocab
static constexpr int LL  = 32;     // caption length
static constexpr int TT  = 31;     // timesteps
static constexpr int XK  = EMB + EE + DD;  // 2560
static constexpr int G4  = 4 * DD;         // 1024
static constexpr int KC  = 10;             // split-K chunks for gates gemm

__device__ int   g_order[NB];
__device__ int   g_target[NB];
__device__ float g_fe[NB * PP * HH];       // 12.8 MB
__device__ float g_mean[NB * EE];
__device__ float g_h[NB * DD];
__device__ float g_c[NB * DD];
__device__ float g_w[NB * PP];
__device__ float g_x[NB * XK];
__device__ float g_gp[KC * NB * G4];       // split-K partials for gates
__device__ float g_gatep[2 * NB * EE];     // split-K partials for gate pre-activation

__device__ __forceinline__ float sigf(float x) { return 1.0f / (1.0f + expf(-x)); }

// ---------------------------------------------------------------------------
// K0: stable descending counting sort of lengths (matches jnp.argsort(-len))
// ---------------------------------------------------------------------------
__global__ void k_order(const int* __restrict__ caplen) {
    if (threadIdx.x == 0) {
        int idx = 0;
        for (int v = LL; v >= 1; --v) {
            for (int i = 0; i < NB; ++i) {
                if (caplen[i] == v) {
                    g_order[idx]  = i;
                    g_target[idx] = v - 1;
                    ++idx;
                }
            }
        }
    }
}

// ---------------------------------------------------------------------------
// K1: mean over positions (float4, streaming loads)
// ---------------------------------------------------------------------------
__global__ void k_mean(const float* __restrict__ feat) {
    int b = blockIdx.x;
    int e0 = blockIdx.y * 1024 + threadIdx.x * 4;
    const float4* base = (const float4*)(feat + (size_t)g_order[b] * PP * EE + e0);
    float4 s = make_float4(0.f, 0.f, 0.f, 0.f);
    #pragma unroll 4
    for (int p = 0; p < PP; ++p) {
        float4 v = __ldcs(base + (size_t)p * (EE / 4));
        s.x += v.x; s.y += v.y; s.z += v.z; s.w += v.w;
    }
    const float inv = 1.0f / PP;
    s.x *= inv; s.y *= inv; s.z *= inv; s.w *= inv;
    *(float4*)(g_mean + b * EE + e0) = s;
}

// ---------------------------------------------------------------------------
// K2: h0 = mean @ W_hid + b_hid ; c0 = mean @ W_cell + b_cell
// ---------------------------------------------------------------------------
__global__ void k_init(const float* __restrict__ W_hid, const float* __restrict__ b_hid,
                       const float* __restrict__ W_cell, const float* __restrict__ b_cell) {
    int b = blockIdx.x, j = threadIdx.x;
    __shared__ float sm[EE];
    for (int e = j; e < EE; e += 256) sm[e] = g_mean[b * EE + e];
    __syncthreads();
    float h = b_hid[j], c = b_cell[j];
    #pragma unroll 4
    for (int e = 0; e < EE; ++e) {
        float m = sm[e];
        h += m * W_hid[e * DD + j];
        c += m * W_cell[e * DD + j];
    }
    g_h[b * DD + j] = h;
    g_c[b * DD + j] = c;
}

// ---------------------------------------------------------------------------
// K3: fe = feat[order] @ Wf + bf.  SGEMM M=12544 K=2048 N=256.
// BM=64 BN=64 BK=16, 4x4 microtile, 256 threads. grid (196, 4) = 784 blocks.
// ---------------------------------------------------------------------------
__global__ void __launch_bounds__(256) k_fe(const float* __restrict__ feat,
                                            const float* __restrict__ Wf,
                                            const float* __restrict__ bf) {
    __shared__ float As[16][68];
    __shared__ float Bs[16][64];
    __shared__ size_t rowoff[64];
    int tid = threadIdx.x;
    int mb = blockIdx.x, nb = blockIdx.y;

    if (tid < 64) {
        int gm = mb * 64 + tid;
        int b = gm / PP, p = gm % PP;
        rowoff[tid] = ((size_t)g_order[b] * PP + p) * EE;
    }
    float acc[4][4] = {};
    int rb = (tid >> 4) * 4, cb = (tid & 15) * 4;
    __syncthreads();

    int ar = tid >> 2, akq = (tid & 3) * 4;
    int bk = tid >> 4, bn = (tid & 15) * 4;

    for (int k0 = 0; k0 < EE; k0 += 16) {
        {
            float4 av = *(const float4*)(feat + rowoff[ar] + k0 + akq);
            As[akq + 0][ar] = av.x; As[akq + 1][ar] = av.y;
            As[akq + 2][ar] = av.z; As[akq + 3][ar] = av.w;
        }
        {
            *(float4*)&Bs[bk][bn] = *(const float4*)(Wf + (size_t)(k0 + bk) * HH + nb * 64 + bn);
        }
        __syncthreads();
        #pragma unroll
        for (int kk = 0; kk < 16; ++kk) {
            float a[4], bv[4];
            *(float4*)a  = *(float4*)&As[kk][rb];
            *(float4*)bv = *(float4*)&Bs[kk][cb];
            #pragma unroll
            for (int i = 0; i < 4; ++i)
                #pragma unroll
                for (int j = 0; j < 4; ++j) acc[i][j] += a[i] * bv[j];
        }
        __syncthreads();
    }
    #pragma unroll
    for (int i = 0; i < 4; ++i) {
        int gm = mb * 64 + rb + i;
        #pragma unroll
        for (int j = 0; j < 4; ++j) {
            int gn = nb * 64 + cb + j;
            g_fe[(size_t)gm * HH + gn] = acc[i][j] + bf[gn];
        }
    }
}

// ---------------------------------------------------------------------------
// K4 (per step): ONE launch, three independent jobs partitioned by blockIdx.x:
//   blocks [0,64):    attention scores + softmax for step t (reads g_h)
//   blocks [64,128):  gate-pre GEMM h @ W_gate, split-K=2 (reads g_h)
//   blocks [128,285): head GEMM for step t-1 (reads g_h; h unchanged since
//                     lstm(t-1), so this is the same value head(t-1) needs)
// ---------------------------------------------------------------------------
__global__ void __launch_bounds__(256) k_stepA(
        const float* __restrict__ Wh, const float* __restrict__ bh,
        const float* __restrict__ We, const float* __restrict__ be,
        const float* __restrict__ W_gate,
        const float* __restrict__ W_head, const float* __restrict__ b_head,
        int t, float* __restrict__ out_att, float* __restrict__ out) {
    int tid = threadIdx.x;
    if (blockIdx.x < NB) {
        // ---- attention scores + softmax, one block per batch row ----
        int b = blockIdx.x;
        int lane = tid & 31, wid = tid >> 5;
        __shared__ float sh[DD], she[HH], se[256], red[8];

        sh[tid] = g_h[b * DD + tid];
        __syncthreads();

        float acc = bh[tid];
        #pragma unroll 8
        for (int k = 0; k < DD; ++k) acc += sh[k] * Wh[k * HH + tid];
        she[tid] = acc;
        __syncthreads();

        const float* febase = g_fe + (size_t)b * PP * HH;
        for (int p = wid; p < PP; p += 8) {
            const float* fr = febase + p * HH;
            float s = 0.f;
            #pragma unroll
            for (int j = lane; j < HH; j += 32) {
                float v = fr[j] + she[j];
                s += fmaxf(v, 0.f) * We[j];
            }
            #pragma unroll
            for (int o = 16; o; o >>= 1) s += __shfl_xor_sync(0xffffffffu, s, o);
            if (lane == 0) se[p] = s + be[0];
        }
        __syncthreads();

        float v = (tid < PP) ? se[tid] : -3.4e38f;
        float m = v;
        #pragma unroll
        for (int o = 16; o; o >>= 1) m = fmaxf(m, __shfl_xor_sync(0xffffffffu, m, o));
        if (lane == 0) red[wid] = m;
        __syncthreads();
        if (tid == 0) {
            float mm = red[0];
            for (int i = 1; i < 8; ++i) mm = fmaxf(mm, red[i]);
            red[0] = mm;
        }
        __syncthreads();
        float mx = red[0];
        __syncthreads();

        float ex = (tid < PP) ? expf(v - mx) : 0.f;
        float s2 = ex;
        #pragma unroll
        for (int o = 16; o; o >>= 1) s2 += __shfl_xor_sync(0xffffffffu, s2, o);
        if (lane == 0) red[wid] = s2;
        __syncthreads();
        if (tid == 0) {
            float ss = 0.f;
            for (int i = 0; i < 8; ++i) ss += red[i];
            red[0] = ss;
        }
        __syncthreads();
        float inv = 1.0f / red[0];
        if (tid < PP) {
            float w = ex * inv;
            g_w[b * PP + tid] = w;
            out_att[((size_t)b * TT + t) * PP + tid] = (g_target[b] > t) ? w : 0.f;
        }
    } else if (blockIdx.x < 2 * NB) {
        // ---- h @ W_gate (64 x 256 x 2048), split-K=2.  BM=64 BN=64 BK=16 ----
        __shared__ float As[16][68];
        __shared__ float Bs[16][64];
        int bid = blockIdx.x - NB;
        int nb = bid & 31, kc = bid >> 5;
        int kbase = kc * 128;
        float acc[4][4] = {};
        int rb = (tid >> 4) * 4, cb = (tid & 15) * 4;

        for (int kt = 0; kt < 128; kt += 16) {
            {
                int r = tid >> 2, kk = (tid & 3) * 4;
                float4 av = *(const float4*)(g_h + r * DD + kbase + kt + kk);
                As[kk + 0][r] = av.x; As[kk + 1][r] = av.y;
                As[kk + 2][r] = av.z; As[kk + 3][r] = av.w;
            }
            {
                int kk = tid >> 4, n = (tid & 15) * 4;
                *(float4*)&Bs[kk][n] =
                    *(const float4*)(W_gate + (size_t)(kbase + kt + kk) * EE + nb * 64 + n);
            }
            __syncthreads();
            #pragma unroll
            for (int kk = 0; kk < 16; ++kk) {
                float a[4], bv[4];
                *(float4*)a  = *(float4*)&As[kk][rb];
                *(float4*)bv = *(float4*)&Bs[kk][cb];
                #pragma unroll
                for (int i = 0; i < 4; ++i)
                    #pragma unroll
                    for (int j = 0; j < 4; ++j) acc[i][j] += a[i] * bv[j];
            }
            __syncthreads();
        }
        #pragma unroll
        for (int i = 0; i < 4; ++i)
            #pragma unroll
            for (int j = 0; j < 4; ++j)
                g_gatep[((size_t)kc * NB + rb + i) * EE + nb * 64 + cb + j] = acc[i][j];
    } else {
        // ---- head GEMM for step t-1: h(64x256) @ W_head(256x10000) ----
        int tprev = t - 1;
        __shared__ float As[16][68];
        __shared__ float Bs[16][64];
        int nb = blockIdx.x - 2 * NB;
        int n0 = nb * 64;
        float acc[4][4] = {};
        int rb = (tid >> 4) * 4, cb = (tid & 15) * 4;

        for (int k0 = 0; k0 < DD; k0 += 16) {
            {
                int r = tid >> 2, kk = (tid & 3) * 4;
                float4 av = *(const float4*)(g_h + r * DD + k0 + kk);
                As[kk + 0][r] = av.x; As[kk + 1][r] = av.y;
                As[kk + 2][r] = av.z; As[kk + 3][r] = av.w;
            }
            {
                int kk = tid >> 4, n = (tid & 15) * 4;
                int gn = n0 + n;
                float4 bv;
                if (gn + 3 < VV) {
                    bv = *(const float4*)(W_head + (size_t)(k0 + kk) * VV + gn);
                } else {
                    bv.x = (gn + 0 < VV) ? W_head[(size_t)(k0 + kk) * VV + gn + 0] : 0.f;
                    bv.y = (gn + 1 < VV) ? W_head[(size_t)(k0 + kk) * VV + gn + 1] : 0.f;
                    bv.z = (gn + 2 < VV) ? W_head[(size_t)(k0 + kk) * VV + gn + 2] : 0.f;
                    bv.w = (gn + 3 < VV) ? W_head[(size_t)(k0 + kk) * VV + gn + 3] : 0.f;
                }
                *(float4*)&Bs[kk][n] = bv;
            }
            __syncthreads();
            #pragma unroll
            for (int kk = 0; kk < 16; ++kk) {
                float a[4], bv[4];
                *(float4*)a  = *(float4*)&As[kk][rb];
                *(float4*)bv = *(float4*)&Bs[kk][cb];
                #pragma unroll
                for (int i = 0; i < 4; ++i)
                    #pragma unroll
                    for (int j = 0; j < 4; ++j) acc[i][j] += a[i] * bv[j];
            }
            __syncthreads();
        }
        #pragma unroll
        for (int i = 0; i < 4; ++i) {
            int b = rb + i;
            bool msk = (g_target[b] > tprev);
            size_t rowbase = ((size_t)b * TT + tprev) * VV;
            #pragma unroll
            for (int j = 0; j < 4; ++j) {
                int gn = n0 + cb + j;
                if (gn < VV) out[rowbase + gn] = msk ? (acc[i][j] + b_head[gn]) : 0.f;
            }
        }
    }
}

// ---------------------------------------------------------------------------
// K6 (per step): ctx = sigmoid(gate) * sum_p w_p feat_p ; assemble x vector.
// grid (NB, 2), 256 threads; float4 per thread; streaming feat loads.
// ---------------------------------------------------------------------------
__global__ void k_ctx(const float* __restrict__ feat, const float* __restrict__ b_gate,
                      const float* __restrict__ emb, const int* __restrict__ tok, int t) {
    int b = blockIdx.x, tid = threadIdx.x;
    __shared__ float sw[PP];
    if (tid < PP) sw[tid] = g_w[b * PP + tid];
    __syncthreads();

    int e0 = blockIdx.y * 1024 + tid * 4;
    const float4* fb = (const float4*)(feat + (size_t)g_order[b] * PP * EE + e0);

    float4 s0 = make_float4(0.f, 0.f, 0.f, 0.f);
    float4 s1 = make_float4(0.f, 0.f, 0.f, 0.f);
    #pragma unroll 2
    for (int p = 0; p < PP; p += 2) {
        float w0 = sw[p], w1 = sw[p + 1];
        float4 v0 = __ldcs(fb + (size_t)p * (EE / 4));
        float4 v1 = __ldcs(fb + (size_t)(p + 1) * (EE / 4));
        s0.x += w0 * v0.x; s0.y += w0 * v0.y; s0.z += w0 * v0.z; s0.w += w0 * v0.w;
        s1.x += w1 * v1.x; s1.y += w1 * v1.y; s1.z += w1 * v1.z; s1.w += w1 * v1.w;
    }
    float4 gp0 = *(const float4*)(g_gatep + (size_t)b * EE + e0);
    float4 gp1 = *(const float4*)(g_gatep + ((size_t)NB + b) * EE + e0);
    float4 bg  = *(const float4*)(b_gate + e0);
    float4 ctx;
    ctx.x = (s0.x + s1.x) * sigf(bg.x + gp0.x + gp1.x);
    ctx.y = (s0.y + s1.y) * sigf(bg.y + gp0.y + gp1.y);
    ctx.z = (s0.z + s1.z) * sigf(bg.z + gp0.z + gp1.z);
    ctx.w = (s0.w + s1.w) * sigf(bg.w + gp0.w + gp1.w);
    *(float4*)(g_x + (size_t)b * XK + EMB + e0) = ctx;

    if (blockIdx.y == 0) {
        int token = tok[g_order[b] * LL + t];
        g_x[b * XK + tid] = emb[(size_t)token * EMB + tid];
        g_x[b * XK + EMB + EE + tid] = g_h[b * DD + tid];
    }
}

// ---------------------------------------------------------------------------
// K7 (per step): gates GEMM  [emb,ctx,h](64x2560) @ [W_ih;W_hh](2560x1024),
// split-K into 10 chunks of 256. Grid (16, 10).
// ---------------------------------------------------------------------------
__global__ void k_gates(const float* __restrict__ W_ih, const float* __restrict__ W_hh) {
    __shared__ float As[16][68];
    __shared__ float Bs[16][64];
    int tid = threadIdx.x;
    int nb = blockIdx.x, kc = blockIdx.y;
    int k0g = kc * 256;
    const float* wbase = (kc < 9) ? (W_ih + (size_t)k0g * G4) : W_hh;
    float acc[4][4] = {};
    int rb = (tid >> 4) * 4, cb = (tid & 15) * 4;

    for (int kt = 0; kt < 256; kt += 16) {
        {
            int r = tid >> 2, kk = (tid & 3) * 4;
            float4 av = *(const float4*)(g_x + r * XK + k0g + kt + kk);
            As[kk + 0][r] = av.x; As[kk + 1][r] = av.y;
            As[kk + 2][r] = av.z; As[kk + 3][r] = av.w;
        }
        {
            int kk = tid >> 4, n = (tid & 15) * 4;
            *(float4*)&Bs[kk][n] = *(const float4*)(wbase + (size_t)(kt + kk) * G4 + nb * 64 + n);
        }
        __syncthreads();
        #pragma unroll
        for (int kk = 0; kk < 16; ++kk) {
            float a[4], bv[4];
            *(float4*)a  = *(float4*)&As[kk][rb];
            *(float4*)bv = *(float4*)&Bs[kk][cb];
            #pragma unroll
            for (int i = 0; i < 4; ++i)
                #pragma unroll
                for (int j = 0; j < 4; ++j) acc[i][j] += a[i] * bv[j];
        }
        __syncthreads();
    }
    #pragma unroll
    for (int i = 0; i < 4; ++i)
        #pragma unroll
        for (int j = 0; j < 4; ++j)
            g_gp[((size_t)kc * NB + rb + i) * G4 + nb * 64 + cb + j] = acc[i][j];
}

// ---------------------------------------------------------------------------
// K8 (per step): LSTM pointwise (sums split-K partials + biases; masked update)
// ---------------------------------------------------------------------------
__global__ void k_lstm(const float* __restrict__ b_ih, const float* __restrict__ b_hh, int t) {
    int b = blockIdx.x, j = threadIdx.x;
    float gi = b_ih[j] + b_hh[j];
    float gf = b_ih[DD + j] + b_hh[DD + j];
    float gg = b_ih[2 * DD + j] + b_hh[2 * DD + j];
    float go = b_ih[3 * DD + j] + b_hh[3 * DD + j];
    #pragma unroll
    for (int kc = 0; kc < KC; ++kc) {
        const float* p = g_gp + ((size_t)kc * NB + b) * G4;
        gi += p[j];
        gf += p[DD + j];
        gg += p[2 * DD + j];
        go += p[3 * DD + j];
    }
    float c = g_c[b * DD + j];
    float cn = sigf(gf) * c + sigf(gi) * tanhf(gg);
    float hn = sigf(go) * tanhf(cn);
    if (g_target[b] > t) {
        g_h[b * DD + j] = hn;
        g_c[b * DD + j] = cn;
    }
}

// ---------------------------------------------------------------------------
// K9: standalone head GEMM (used only for the final step t = TT-1)
// ---------------------------------------------------------------------------
__global__ void __launch_bounds__(256) k_head(
        const float* __restrict__ W_head, const float* __restrict__ b_head,
        int t, float* __restrict__ out) {
    __shared__ float As[16][68];
    __shared__ float Bs[16][64];
    int tid = threadIdx.x, nb = blockIdx.x;
    int n0 = nb * 64;
    float acc[4][4] = {};
    int rb = (tid >> 4) * 4, cb = (tid & 15) * 4;

    for (int k0 = 0; k0 < DD; k0 += 16) {
        {
            int r = tid >> 2, kk = (tid & 3) * 4;
            float4 av = *(const float4*)(g_h + r * DD + k0 + kk);
            As[kk + 0][r] = av.x; As[kk + 1][r] = av.y;
            As[kk + 2][r] = av.z; As[kk + 3][r] = av.w;
        }
        {
            int kk = tid >> 4, n = (tid & 15) * 4;
            int gn = n0 + n;
            float4 bv;
            if (gn + 3 < VV) {
                bv = *(const float4*)(W_head + (size_t)(k0 + kk) * VV + gn);
            } else {
                bv.x = (gn + 0 < VV) ? W_head[(size_t)(k0 + kk) * VV + gn + 0] : 0.f;
                bv.y = (gn + 1 < VV) ? W_head[(size_t)(k0 + kk) * VV + gn + 1] : 0.f;
                bv.z = (gn + 2 < VV) ? W_head[(size_t)(k0 + kk) * VV + gn + 2] : 0.f;
                bv.w = (gn + 3 < VV) ? W_head[(size_t)(k0 + kk) * VV + gn + 3] : 0.f;
            }
            *(float4*)&Bs[kk][n] = bv;
        }
        __syncthreads();
        #pragma unroll
        for (int kk = 0; kk < 16; ++kk) {
            float a[4], bv[4];
            *(float4*)a  = *(float4*)&As[kk][rb];
            *(float4*)bv = *(float4*)&Bs[kk][cb];
            #pragma unroll
            for (int i = 0; i < 4; ++i)
                #pragma unroll
                for (int j = 0; j < 4; ++j) acc[i][j] += a[i] * bv[j];
        }
        __syncthreads();
    }
    #pragma unroll
    for (int i = 0; i < 4; ++i) {
        int b = rb + i;
        bool msk = (g_target[b] > t);
        size_t rowbase = ((size_t)b * TT + t) * VV;
        #pragma unroll
        for (int j = 0; j < 4; ++j) {
            int gn = n0 + cb + j;
            if (gn < VV) out[rowbase + gn] = msk ? (acc[i][j] + b_head[gn]) : 0.f;
        }
    }
}

// ---------------------------------------------------------------------------
extern "C" void kernel_launch(void* const* d_in, const int* in_sizes, int n_in,
                              void* d_out, int out_size) {
    const float* feat   = (const float*)d_in[0];
    const int*   tok    = (const int*)d_in[1];
    const int*   caplen = (const int*)d_in[2];
    const float* Wf     = (const float*)d_in[3];
    const float* bf     = (const float*)d_in[4];
    const float* Wh     = (const float*)d_in[5];
    const float* bh     = (const float*)d_in[6];
    const float* We     = (const float*)d_in[7];
    const float* be     = (const float*)d_in[8];
    const float* emb    = (const float*)d_in[9];
    const float* W_ih   = (const float*)d_in[10];
    const float* b_ih   = (const float*)d_in[11];
    const float* W_hh   = (const float*)d_in[12];
    const float* b_hh   = (const float*)d_in[13];
    const float* W_hid  = (const float*)d_in[14];
    const float* b_hid  = (const float*)d_in[15];
    const float* W_cell = (const float*)d_in[16];
    const float* b_cell = (const float*)d_in[17];
    const float* W_gate = (const float*)d_in[18];
    const float* b_gate = (const float*)d_in[19];
    const float* W_head = (const float*)d_in[20];
    const float* b_head = (const float*)d_in[21];

    float* out = (float*)d_out;
    float* out_att = out + (size_t)NB * TT * VV;

    k_order<<<1, 32>>>(caplen);
    k_mean<<<dim3(NB, 2), 256>>>(feat);
    k_init<<<NB, 256>>>(W_hid, b_hid, W_cell, b_cell);
    k_fe<<<dim3(196, 4), 256>>>(feat, Wf, bf);

    for (int t = 0; t < TT; ++t) {
        // att(t) + gpre(t) + head(t-1) fused in one launch (t=0: no head blocks)
        int nblk = (t == 0) ? 2 * NB : 2 * NB + 157;
        k_stepA<<<nblk, 256>>>(Wh, bh, We, be, W_gate, W_head, b_head, t, out_att, out);
        k_ctx<<<dim3(NB, 2), 256>>>(feat, b_gate, emb, tok, t);
        k_gates<<<dim3(16, 10), 256>>>(W_ih, W_hh);
        k_lstm<<<NB, 256>>>(b_ih, b_hh, t);
    }
    k_head<<<157, 256>>>(W_head, b_head, TT - 1, out);
}

// round 4
// speedup vs baseline: 1.4383x; 1.1429x over previous
#include <cuda_runtime.h>

static constexpr int NB  = 64;     // batch
static constexpr int PP  = 196;    // spatial positions
static constexpr int EE  = 2048;   // feature dim
static constexpr int DD  = 256;    // hidden
static constexpr int HH  = 256;    // attention hidden
static constexpr int EMB = 256;    // embedding
static constexpr int VV  = 10000;  // vocab
static constexpr int LL  = 32;     // caption length
static constexpr int TT  = 31;     // timesteps
static constexpr int XK  = EMB + EE + DD;  // 2560
static constexpr int G4  = 4 * DD;         // 1024
static constexpr int KC  = 10;             // split-K chunks for gates gemm

__device__ int   g_order[NB];
__device__ int   g_target[NB];
__device__ float g_fe[NB * PP * HH];       // 12.8 MB
__device__ float g_mean[NB * EE];
__device__ float g_h[NB * DD];
__device__ float g_c[NB * DD];
__device__ float g_w[NB * PP];
__device__ float g_x[NB * XK];
__device__ float g_gp[KC * NB * G4];       // split-K partials for gates
__device__ float g_gatep[2 * NB * EE];     // split-K partials for gate pre-activation

__device__ __forceinline__ float sigf(float x) { return 1.0f / (1.0f + expf(-x)); }

// ---------------------------------------------------------------------------
// K0: stable descending counting sort of lengths (matches jnp.argsort(-len))
// ---------------------------------------------------------------------------
__global__ void k_order(const int* __restrict__ caplen) {
    if (threadIdx.x == 0) {
        int idx = 0;
        for (int v = LL; v >= 1; --v) {
            for (int i = 0; i < NB; ++i) {
                if (caplen[i] == v) {
                    g_order[idx]  = i;
                    g_target[idx] = v - 1;
                    ++idx;
                }
            }
        }
    }
}

// ---------------------------------------------------------------------------
// K3: fused launch, grid (98, 5):
//   blockIdx.y < 4 : fe = feat[order] @ Wf + bf.  SGEMM M=12544 K=2048 N=256.
//                    BM=128 BN=64 BK=16, 8x4 microtile, 256 threads.
//   blockIdx.y == 4: mean over positions (blocks 0..63; independent of fe)
// ---------------------------------------------------------------------------
__global__ void __launch_bounds__(256) k_fe(const float* __restrict__ feat,
                                            const float* __restrict__ Wf,
                                            const float* __restrict__ bf) {
    int tid = threadIdx.x;
    int mb = blockIdx.x, nb = blockIdx.y;

    if (nb == 4) {
        // ---- mean: one block per batch row (blocks >= NB exit) ----
        if (mb >= NB) return;
        int b = mb;
        const float4* base = (const float4*)(feat + (size_t)g_order[b] * PP * EE);
        float4 sA = make_float4(0.f, 0.f, 0.f, 0.f);
        float4 sB = make_float4(0.f, 0.f, 0.f, 0.f);
        #pragma unroll 2
        for (int p = 0; p < PP; ++p) {
            float4 v0 = __ldcs(base + (size_t)p * (EE / 4) + tid);
            float4 v1 = __ldcs(base + (size_t)p * (EE / 4) + tid + 256);
            sA.x += v0.x; sA.y += v0.y; sA.z += v0.z; sA.w += v0.w;
            sB.x += v1.x; sB.y += v1.y; sB.z += v1.z; sB.w += v1.w;
        }
        const float inv = 1.0f / PP;
        sA.x *= inv; sA.y *= inv; sA.z *= inv; sA.w *= inv;
        sB.x *= inv; sB.y *= inv; sB.z *= inv; sB.w *= inv;
        *(float4*)(g_mean + b * EE + tid * 4)        = sA;
        *(float4*)(g_mean + b * EE + 1024 + tid * 4) = sB;
        return;
    }

    // ---- fe GEMM tile ----
    __shared__ float As[16][132];
    __shared__ float Bs[16][64];
    __shared__ size_t rowoff[128];

    if (tid < 128) {
        int gm = mb * 128 + tid;
        int b = gm / PP, p = gm % PP;
        rowoff[tid] = ((size_t)g_order[b] * PP + p) * EE;
    }
    float acc[8][4] = {};
    int rb = (tid >> 4) * 8, cb = (tid & 15) * 4;
    __syncthreads();

    int ar = tid >> 1, ak = (tid & 1) * 8;
    int bk = tid >> 4, bn = (tid & 15) * 4;

    for (int k0 = 0; k0 < EE; k0 += 16) {
        {
            const float* src = feat + rowoff[ar] + k0 + ak;
            float4 a0 = *(const float4*)(src);
            float4 a1 = *(const float4*)(src + 4);
            As[ak + 0][ar] = a0.x; As[ak + 1][ar] = a0.y;
            As[ak + 2][ar] = a0.z; As[ak + 3][ar] = a0.w;
            As[ak + 4][ar] = a1.x; As[ak + 5][ar] = a1.y;
            As[ak + 6][ar] = a1.z; As[ak + 7][ar] = a1.w;
        }
        {
            *(float4*)&Bs[bk][bn] = *(const float4*)(Wf + (size_t)(k0 + bk) * HH + nb * 64 + bn);
        }
        __syncthreads();
        #pragma unroll
        for (int kk = 0; kk < 16; ++kk) {
            float a[8], bv[4];
            *(float4*)(a)     = *(float4*)&As[kk][rb];
            *(float4*)(a + 4) = *(float4*)&As[kk][rb + 4];
            *(float4*)(bv)    = *(float4*)&Bs[kk][cb];
            #pragma unroll
            for (int i = 0; i < 8; ++i)
                #pragma unroll
                for (int j = 0; j < 4; ++j) acc[i][j] += a[i] * bv[j];
        }
        __syncthreads();
    }
    #pragma unroll
    for (int i = 0; i < 8; ++i) {
        int gm = mb * 128 + rb + i;
        #pragma unroll
        for (int j = 0; j < 4; ++j) {
            int gn = nb * 64 + cb + j;
            g_fe[(size_t)gm * HH + gn] = acc[i][j] + bf[gn];
        }
    }
}

// ---------------------------------------------------------------------------
// K2: h0 = mean @ W_hid + b_hid ; c0 = mean @ W_cell + b_cell
// ---------------------------------------------------------------------------
__global__ void k_init(const float* __restrict__ W_hid, const float* __restrict__ b_hid,
                       const float* __restrict__ W_cell, const float* __restrict__ b_cell) {
    int b = blockIdx.x, j = threadIdx.x;
    __shared__ float sm[EE];
    for (int e = j; e < EE; e += 256) sm[e] = g_mean[b * EE + e];
    __syncthreads();
    float h = b_hid[j], c = b_cell[j];
    #pragma unroll 4
    for (int e = 0; e < EE; ++e) {
        float m = sm[e];
        h += m * W_hid[e * DD + j];
        c += m * W_cell[e * DD + j];
    }
    g_h[b * DD + j] = h;
    g_c[b * DD + j] = c;
}

// ---------------------------------------------------------------------------
// K4 (per step): ONE launch, three independent jobs partitioned by blockIdx.x:
//   blocks [0,64):    attention scores + softmax for step t (reads g_h)
//   blocks [64,128):  gate-pre GEMM h @ W_gate, split-K=2 (reads g_h)
//   blocks [128,285): head GEMM for step t-1 (reads g_h, unchanged since lstm(t-1))
// ---------------------------------------------------------------------------
__global__ void __launch_bounds__(256) k_stepA(
        const float* __restrict__ Wh, const float* __restrict__ bh,
        const float* __restrict__ We, const float* __restrict__ be,
        const float* __restrict__ W_gate,
        const float* __restrict__ W_head, const float* __restrict__ b_head,
        int t, float* __restrict__ out_att, float* __restrict__ out) {
    int tid = threadIdx.x;
    if (blockIdx.x < NB) {
        // ---- attention scores + softmax, one block per batch row ----
        int b = blockIdx.x;
        int lane = tid & 31, wid = tid >> 5;
        __shared__ float sh[DD], she[HH], se[256], red[8];

        sh[tid] = g_h[b * DD + tid];
        __syncthreads();

        float acc = bh[tid];
        #pragma unroll 8
        for (int k = 0; k < DD; ++k) acc += sh[k] * Wh[k * HH + tid];
        she[tid] = acc;
        __syncthreads();

        const float* febase = g_fe + (size_t)b * PP * HH;
        for (int p = wid; p < PP; p += 8) {
            const float* fr = febase + p * HH;
            float s = 0.f;
            #pragma unroll
            for (int j = lane; j < HH; j += 32) {
                float v = fr[j] + she[j];
                s += fmaxf(v, 0.f) * We[j];
            }
            #pragma unroll
            for (int o = 16; o; o >>= 1) s += __shfl_xor_sync(0xffffffffu, s, o);
            if (lane == 0) se[p] = s + be[0];
        }
        __syncthreads();

        float v = (tid < PP) ? se[tid] : -3.4e38f;
        float m = v;
        #pragma unroll
        for (int o = 16; o; o >>= 1) m = fmaxf(m, __shfl_xor_sync(0xffffffffu, m, o));
        if (lane == 0) red[wid] = m;
        __syncthreads();
        if (tid == 0) {
            float mm = red[0];
            for (int i = 1; i < 8; ++i) mm = fmaxf(mm, red[i]);
            red[0] = mm;
        }
        __syncthreads();
        float mx = red[0];
        __syncthreads();

        float ex = (tid < PP) ? expf(v - mx) : 0.f;
        float s2 = ex;
        #pragma unroll
        for (int o = 16; o; o >>= 1) s2 += __shfl_xor_sync(0xffffffffu, s2, o);
        if (lane == 0) red[wid] = s2;
        __syncthreads();
        if (tid == 0) {
            float ss = 0.f;
            for (int i = 0; i < 8; ++i) ss += red[i];
            red[0] = ss;
        }
        __syncthreads();
        float inv = 1.0f / red[0];
        if (tid < PP) {
            float w = ex * inv;
            g_w[b * PP + tid] = w;
            out_att[((size_t)b * TT + t) * PP + tid] = (g_target[b] > t) ? w : 0.f;
        }
    } else if (blockIdx.x < 2 * NB) {
        // ---- h @ W_gate (64 x 256 x 2048), split-K=2.  BM=64 BN=64 BK=16 ----
        __shared__ float As[16][68];
        __shared__ float Bs[16][64];
        int bid = blockIdx.x - NB;
        int nb = bid & 31, kc = bid >> 5;
        int kbase = kc * 128;
        float acc[4][4] = {};
        int rb = (tid >> 4) * 4, cb = (tid & 15) * 4;

        for (int kt = 0; kt < 128; kt += 16) {
            {
                int r = tid >> 2, kk = (tid & 3) * 4;
                float4 av = *(const float4*)(g_h + r * DD + kbase + kt + kk);
                As[kk + 0][r] = av.x; As[kk + 1][r] = av.y;
                As[kk + 2][r] = av.z; As[kk + 3][r] = av.w;
            }
            {
                int kk = tid >> 4, n = (tid & 15) * 4;
                *(float4*)&Bs[kk][n] =
                    *(const float4*)(W_gate + (size_t)(kbase + kt + kk) * EE + nb * 64 + n);
            }
            __syncthreads();
            #pragma unroll
            for (int kk = 0; kk < 16; ++kk) {
                float a[4], bv[4];
                *(float4*)a  = *(float4*)&As[kk][rb];
                *(float4*)bv = *(float4*)&Bs[kk][cb];
                #pragma unroll
                for (int i = 0; i < 4; ++i)
                    #pragma unroll
                    for (int j = 0; j < 4; ++j) acc[i][j] += a[i] * bv[j];
            }
            __syncthreads();
        }
        #pragma unroll
        for (int i = 0; i < 4; ++i)
            #pragma unroll
            for (int j = 0; j < 4; ++j)
                g_gatep[((size_t)kc * NB + rb + i) * EE + nb * 64 + cb + j] = acc[i][j];
    } else {
        // ---- head GEMM for step t-1: h(64x256) @ W_head(256x10000) ----
        int tprev = t - 1;
        __shared__ float As[16][68];
        __shared__ float Bs[16][64];
        int nb = blockIdx.x - 2 * NB;
        int n0 = nb * 64;
        float acc[4][4] = {};
        int rb = (tid >> 4) * 4, cb = (tid & 15) * 4;

        for (int k0 = 0; k0 < DD; k0 += 16) {
            {
                int r = tid >> 2, kk = (tid & 3) * 4;
                float4 av = *(const float4*)(g_h + r * DD + k0 + kk);
                As[kk + 0][r] = av.x; As[kk + 1][r] = av.y;
                As[kk + 2][r] = av.z; As[kk + 3][r] = av.w;
            }
            {
                int kk = tid >> 4, n = (tid & 15) * 4;
                int gn = n0 + n;
                float4 bv;
                if (gn + 3 < VV) {
                    bv = *(const float4*)(W_head + (size_t)(k0 + kk) * VV + gn);
                } else {
                    bv.x = (gn + 0 < VV) ? W_head[(size_t)(k0 + kk) * VV + gn + 0] : 0.f;
                    bv.y = (gn + 1 < VV) ? W_head[(size_t)(k0 + kk) * VV + gn + 1] : 0.f;
                    bv.z = (gn + 2 < VV) ? W_head[(size_t)(k0 + kk) * VV + gn + 2] : 0.f;
                    bv.w = (gn + 3 < VV) ? W_head[(size_t)(k0 + kk) * VV + gn + 3] : 0.f;
                }
                *(float4*)&Bs[kk][n] = bv;
            }
            __syncthreads();
            #pragma unroll
            for (int kk = 0; kk < 16; ++kk) {
                float a[4], bv[4];
                *(float4*)a  = *(float4*)&As[kk][rb];
                *(float4*)bv = *(float4*)&Bs[kk][cb];
                #pragma unroll
                for (int i = 0; i < 4; ++i)
                    #pragma unroll
                    for (int j = 0; j < 4; ++j) acc[i][j] += a[i] * bv[j];
            }
            __syncthreads();
        }
        #pragma unroll
        for (int i = 0; i < 4; ++i) {
            int b = rb + i;
            bool msk = (g_target[b] > tprev);
            size_t rowbase = ((size_t)b * TT + tprev) * VV;
            #pragma unroll
            for (int j = 0; j < 4; ++j) {
                int gn = n0 + cb + j;
                if (gn < VV) out[rowbase + gn] = msk ? (acc[i][j] + b_head[gn]) : 0.f;
            }
        }
    }
}

// ---------------------------------------------------------------------------
// K6 (per step): ctx = sigmoid(gate) * sum_p w_p feat_p ; assemble x vector.
// grid (NB, 4), 128 threads; float4/thread; 4-deep unroll for MLP; streaming.
// ---------------------------------------------------------------------------
__global__ void __launch_bounds__(128) k_ctx(
        const float* __restrict__ feat, const float* __restrict__ b_gate,
        const float* __restrict__ emb, const int* __restrict__ tok, int t) {
    int b = blockIdx.x, tid = threadIdx.x;
    __shared__ float sw[PP];
    if (tid < PP - 128) sw[128 + tid] = g_w[b * PP + 128 + tid];
    sw[tid] = g_w[b * PP + tid];
    __syncthreads();

    int e0 = blockIdx.y * 512 + tid * 4;
    const float4* fb = (const float4*)(feat + (size_t)g_order[b] * PP * EE + e0);

    float4 s0 = make_float4(0.f, 0.f, 0.f, 0.f);
    float4 s1 = make_float4(0.f, 0.f, 0.f, 0.f);
    float4 s2 = make_float4(0.f, 0.f, 0.f, 0.f);
    float4 s3 = make_float4(0.f, 0.f, 0.f, 0.f);
    for (int p = 0; p < PP; p += 4) {
        float w0 = sw[p], w1 = sw[p + 1], w2 = sw[p + 2], w3 = sw[p + 3];
        float4 v0 = __ldcs(fb + (size_t)(p + 0) * (EE / 4));
        float4 v1 = __ldcs(fb + (size_t)(p + 1) * (EE / 4));
        float4 v2 = __ldcs(fb + (size_t)(p + 2) * (EE / 4));
        float4 v3 = __ldcs(fb + (size_t)(p + 3) * (EE / 4));
        s0.x += w0 * v0.x; s0.y += w0 * v0.y; s0.z += w0 * v0.z; s0.w += w0 * v0.w;
        s1.x += w1 * v1.x; s1.y += w1 * v1.y; s1.z += w1 * v1.z; s1.w += w1 * v1.w;
        s2.x += w2 * v2.x; s2.y += w2 * v2.y; s2.z += w2 * v2.z; s2.w += w2 * v2.w;
        s3.x += w3 * v3.x; s3.y += w3 * v3.y; s3.z += w3 * v3.z; s3.w += w3 * v3.w;
    }
    float4 sum;
    sum.x = (s0.x + s1.x) + (s2.x + s3.x);
    sum.y = (s0.y + s1.y) + (s2.y + s3.y);
    sum.z = (s0.z + s1.z) + (s2.z + s3.z);
    sum.w = (s0.w + s1.w) + (s2.w + s3.w);

    float4 gp0 = *(const float4*)(g_gatep + (size_t)b * EE + e0);
    float4 gp1 = *(const float4*)(g_gatep + ((size_t)NB + b) * EE + e0);
    float4 bg  = *(const float4*)(b_gate + e0);
    float4 ctx;
    ctx.x = sum.x * sigf(bg.x + gp0.x + gp1.x);
    ctx.y = sum.y * sigf(bg.y + gp0.y + gp1.y);
    ctx.z = sum.z * sigf(bg.z + gp0.z + gp1.z);
    ctx.w = sum.w * sigf(bg.w + gp0.w + gp1.w);
    *(float4*)(g_x + (size_t)b * XK + EMB + e0) = ctx;

    if (blockIdx.y == 0) {
        int token = tok[g_order[b] * LL + t];
        g_x[b * XK + tid] = emb[(size_t)token * EMB + tid];
        g_x[b * XK + tid + 128] = emb[(size_t)token * EMB + tid + 128];
        g_x[b * XK + EMB + EE + tid] = g_h[b * DD + tid];
        g_x[b * XK + EMB + EE + tid + 128] = g_h[b * DD + tid + 128];
    }
}

// ---------------------------------------------------------------------------
// K7 (per step): gates GEMM  [emb,ctx,h](64x2560) @ [W_ih;W_hh](2560x1024),
// split-K into 10 chunks of 256. Grid (16, 10).
// ---------------------------------------------------------------------------
__global__ void k_gates(const float* __restrict__ W_ih, const float* __restrict__ W_hh) {
    __shared__ float As[16][68];
    __shared__ float Bs[16][64];
    int tid = threadIdx.x;
    int nb = blockIdx.x, kc = blockIdx.y;
    int k0g = kc * 256;
    const float* wbase = (kc < 9) ? (W_ih + (size_t)k0g * G4) : W_hh;
    float acc[4][4] = {};
    int rb = (tid >> 4) * 4, cb = (tid & 15) * 4;

    for (int kt = 0; kt < 256; kt += 16) {
        {
            int r = tid >> 2, kk = (tid & 3) * 4;
            float4 av = *(const float4*)(g_x + r * XK + k0g + kt + kk);
            As[kk + 0][r] = av.x; As[kk + 1][r] = av.y;
            As[kk + 2][r] = av.z; As[kk + 3][r] = av.w;
        }
        {
            int kk = tid >> 4, n = (tid & 15) * 4;
            *(float4*)&Bs[kk][n] = *(const float4*)(wbase + (size_t)(kt + kk) * G4 + nb * 64 + n);
        }
        __syncthreads();
        #pragma unroll
        for (int kk = 0; kk < 16; ++kk) {
            float a[4], bv[4];
            *(float4*)a  = *(float4*)&As[kk][rb];
            *(float4*)bv = *(float4*)&Bs[kk][cb];
            #pragma unroll
            for (int i = 0; i < 4; ++i)
                #pragma unroll
                for (int j = 0; j < 4; ++j) acc[i][j] += a[i] * bv[j];
        }
        __syncthreads();
    }
    #pragma unroll
    for (int i = 0; i < 4; ++i)
        #pragma unroll
        for (int j = 0; j < 4; ++j)
            g_gp[((size_t)kc * NB + rb + i) * G4 + nb * 64 + cb + j] = acc[i][j];
}

// ---------------------------------------------------------------------------
// K8 (per step): LSTM pointwise (sums split-K partials + biases; masked update)
// ---------------------------------------------------------------------------
__global__ void k_lstm(const float* __restrict__ b_ih, const float* __restrict__ b_hh, int t) {
    int b = blockIdx.x, j = threadIdx.x;
    float gi = b_ih[j] + b_hh[j];
    float gf = b_ih[DD + j] + b_hh[DD + j];
    float gg = b_ih[2 * DD + j] + b_hh[2 * DD + j];
    float go = b_ih[3 * DD + j] + b_hh[3 * DD + j];
    #pragma unroll
    for (int kc = 0; kc < KC; ++kc) {
        const float* p = g_gp + ((size_t)kc * NB + b) * G4;
        gi += p[j];
        gf += p[DD + j];
        gg += p[2 * DD + j];
        go += p[3 * DD + j];
    }
    float c = g_c[b * DD + j];
    float cn = sigf(gf) * c + sigf(gi) * tanhf(gg);
    float hn = sigf(go) * tanhf(cn);
    if (g_target[b] > t) {
        g_h[b * DD + j] = hn;
        g_c[b * DD + j] = cn;
    }
}

// ---------------------------------------------------------------------------
// K9: standalone head GEMM (used only for the final step t = TT-1)
// ---------------------------------------------------------------------------
__global__ void __launch_bounds__(256) k_head(
        const float* __restrict__ W_head, const float* __restrict__ b_head,
        int t, float* __restrict__ out) {
    __shared__ float As[16][68];
    __shared__ float Bs[16][64];
    int tid = threadIdx.x, nb = blockIdx.x;
    int n0 = nb * 64;
    float acc[4][4] = {};
    int rb = (tid >> 4) * 4, cb = (tid & 15) * 4;

    for (int k0 = 0; k0 < DD; k0 += 16) {
        {
            int r = tid >> 2, kk = (tid & 3) * 4;
            float4 av = *(const float4*)(g_h + r * DD + k0 + kk);
            As[kk + 0][r] = av.x; As[kk + 1][r] = av.y;
            As[kk + 2][r] = av.z; As[kk + 3][r] = av.w;
        }
        {
            int kk = tid >> 4, n = (tid & 15) * 4;
            int gn = n0 + n;
            float4 bv;
            if (gn + 3 < VV) {
                bv = *(const float4*)(W_head + (size_t)(k0 + kk) * VV + gn);
            } else {
                bv.x = (gn + 0 < VV) ? W_head[(size_t)(k0 + kk) * VV + gn + 0] : 0.f;
                bv.y = (gn + 1 < VV) ? W_head[(size_t)(k0 + kk) * VV + gn + 1] : 0.f;
                bv.z = (gn + 2 < VV) ? W_head[(size_t)(k0 + kk) * VV + gn + 2] : 0.f;
                bv.w = (gn + 3 < VV) ? W_head[(size_t)(k0 + kk) * VV + gn + 3] : 0.f;
            }
            *(float4*)&Bs[kk][n] = bv;
        }
        __syncthreads();
        #pragma unroll
        for (int kk = 0; kk < 16; ++kk) {
            float a[4], bv[4];
            *(float4*)a  = *(float4*)&As[kk][rb];
            *(float4*)bv = *(float4*)&Bs[kk][cb];
            #pragma unroll
            for (int i = 0; i < 4; ++i)
                #pragma unroll
                for (int j = 0; j < 4; ++j) acc[i][j] += a[i] * bv[j];
        }
        __syncthreads();
    }
    #pragma unroll
    for (int i = 0; i < 4; ++i) {
        int b = rb + i;
        bool msk = (g_target[b] > t);
        size_t rowbase = ((size_t)b * TT + t) * VV;
        #pragma unroll
        for (int j = 0; j < 4; ++j) {
            int gn = n0 + cb + j;
            if (gn < VV) out[rowbase + gn] = msk ? (acc[i][j] + b_head[gn]) : 0.f;
        }
    }
}

// ---------------------------------------------------------------------------
extern "C" void kernel_launch(void* const* d_in, const int* in_sizes, int n_in,
                              void* d_out, int out_size) {
    const float* feat   = (const float*)d_in[0];
    const int*   tok    = (const int*)d_in[1];
    const int*   caplen = (const int*)d_in[2];
    const float* Wf     = (const float*)d_in[3];
    const float* bf     = (const float*)d_in[4];
    const float* Wh     = (const float*)d_in[5];
    const float* bh     = (const float*)d_in[6];
    const float* We     = (const float*)d_in[7];
    const float* be     = (const float*)d_in[8];
    const float* emb    = (const float*)d_in[9];
    const float* W_ih   = (const float*)d_in[10];
    const float* b_ih   = (const float*)d_in[11];
    const float* W_hh   = (const float*)d_in[12];
    const float* b_hh   = (const float*)d_in[13];
    const float* W_hid  = (const float*)d_in[14];
    const float* b_hid  = (const float*)d_in[15];
    const float* W_cell = (const float*)d_in[16];
    const float* b_cell = (const float*)d_in[17];
    const float* W_gate = (const float*)d_in[18];
    const float* b_gate = (const float*)d_in[19];
    const float* W_head = (const float*)d_in[20];
    const float* b_head = (const float*)d_in[21];

    float* out = (float*)d_out;
    float* out_att = out + (size_t)NB * TT * VV;

    k_order<<<1, 32>>>(caplen);
    k_fe<<<dim3(98, 5), 256>>>(feat, Wf, bf);   // fe GEMM + mean fused
    k_init<<<NB, 256>>>(W_hid, b_hid, W_cell, b_cell);

    for (int t = 0; t < TT; ++t) {
        // att(t) + gpre(t) + head(t-1) fused in one launch (t=0: no head blocks)
        int nblk = (t == 0) ? 2 * NB : 2 * NB + 157;
        k_stepA<<<nblk, 256>>>(Wh, bh, We, be, W_gate, W_head, b_head, t, out_att, out);
        k_ctx<<<dim3(NB, 4), 128>>>(feat, b_gate, emb, tok, t);
        k_gates<<<dim3(16, 10), 256>>>(W_ih, W_hh);
        k_lstm<<<NB, 256>>>(b_ih, b_hh, t);
    }
    k_head<<<157, 256>>>(W_head, b_head, TT - 1, out);
}